// round 1
// baseline (speedup 1.0000x reference)
#include <cuda_runtime.h>
#include <cuda_bf16.h>
#include <mma.h>
#include <cstdint>
#include <cstddef>

using namespace nvcuda;

// ---------------- problem constants ----------------
#define KB     8
#define KT     8192
#define KS     64
#define KVD    256
#define KLD    768
#define KE     1024
#define KH     16
#define KHD    64
#define KMV    (KB*KT)     /* 65536 */
#define KML    (KB*KS)     /* 512   */
#define QK_SCALE 0.125f

// ---------------- scratch layout (single __device__ arena) ----------------
// bf16 intermediates + fp32 accumulators + bf16 weights
#define OFF_VN   ((size_t)0)                      /* [65536,256] bf16 */
#define OFF_QIN  ((size_t)33554432)               /* [65536,256] bf16 */
#define OFF_Q    ((size_t)67108864)               /* [65536,1024] bf16 */
#define OFF_VV   ((size_t)201326592)              /* [65536,1024] bf16 */
#define OFF_OV   ((size_t)335544320)              /* [65536,1024] bf16 */
#define OFF_LN   ((size_t)469762048)              /* [512,768] bf16 */
#define OFF_K    ((size_t)470548480)              /* [512,1024] bf16 */
#define OFF_VL   ((size_t)471597056)              /* [512,1024] bf16 */
#define OFF_MG   ((size_t)472645632)              /* [512,1024] bf16 */
#define OFF_U    ((size_t)473694208)              /* [8,16,64,64] f32 */
#define OFF_Z    ((size_t)475791360)              /* [8,16,64] f32 */
#define OFF_WQ   ((size_t)475824128)
#define OFF_WVV  ((size_t)476348416)
#define OFF_WOV  ((size_t)476872704)
#define OFF_WK   ((size_t)477396992)
#define OFF_WVL  ((size_t)478969856)
#define OFF_WOL  ((size_t)480542720)
#define SCRATCH_BYTES ((size_t)482115584)

__device__ __align__(256) unsigned char g_scratch[SCRATCH_BYTES];

// ---------------- small helpers ----------------
__device__ __forceinline__ uint32_t pk_bf2(float a, float b) {
    __nv_bfloat162 t = __floats2bfloat162_rn(a, b);
    return *reinterpret_cast<uint32_t*>(&t);
}

// ---------------- zero U/Z ----------------
__global__ void zero_kernel() {
    size_t i = (size_t)blockIdx.x * 256 + threadIdx.x;
    const size_t n = (size_t)KB*KH*KS*KHD + (size_t)KB*KH*KS;
    float* p = (float*)(g_scratch + OFF_U);
    if (i < n) p[i] = 0.0f;
}

// ---------------- fp32 -> bf16 convert ----------------
__global__ void cvt_kernel(const float* __restrict__ s, __nv_bfloat16* __restrict__ d, int n) {
    int i = blockIdx.x * 256 + threadIdx.x;
    if (i < n) d[i] = __float2bfloat16(s[i]);
}

// ---------------- LayerNorm(v) + v_pos: one warp per 256-wide row ----------------
__global__ __launch_bounds__(256) void lnv_kernel(const float* __restrict__ v,
                                                  const float* __restrict__ vp,
                                                  const float* __restrict__ w,
                                                  const float* __restrict__ b) {
    int row  = blockIdx.x * 8 + (threadIdx.x >> 5);
    int lane = threadIdx.x & 31;
    const float4* vr = reinterpret_cast<const float4*>(v + (size_t)row * KVD) + lane * 2;
    float4 x0 = vr[0], x1 = vr[1];
    float s = x0.x + x0.y + x0.z + x0.w + x1.x + x1.y + x1.z + x1.w;
    float q = x0.x*x0.x + x0.y*x0.y + x0.z*x0.z + x0.w*x0.w
            + x1.x*x1.x + x1.y*x1.y + x1.z*x1.z + x1.w*x1.w;
    #pragma unroll
    for (int o = 16; o > 0; o >>= 1) {
        s += __shfl_xor_sync(0xffffffffu, s, o);
        q += __shfl_xor_sync(0xffffffffu, q, o);
    }
    float mu   = s * (1.0f / KVD);
    float var  = q * (1.0f / KVD) - mu * mu;
    float rstd = rsqrtf(var + 1e-5f);

    const float4* vpr = reinterpret_cast<const float4*>(vp + (size_t)row * KVD) + lane * 2;
    float4 p0 = vpr[0], p1 = vpr[1];
    const float4* w4 = reinterpret_cast<const float4*>(w) + lane * 2;
    const float4* b4 = reinterpret_cast<const float4*>(b) + lane * 2;
    float4 wa = w4[0], wb = w4[1], ba = b4[0], bb = b4[1];

    float n0 = (x0.x - mu) * rstd * wa.x + ba.x;
    float n1 = (x0.y - mu) * rstd * wa.y + ba.y;
    float n2 = (x0.z - mu) * rstd * wa.z + ba.z;
    float n3 = (x0.w - mu) * rstd * wa.w + ba.w;
    float n4 = (x1.x - mu) * rstd * wb.x + bb.x;
    float n5 = (x1.y - mu) * rstd * wb.y + bb.y;
    float n6 = (x1.z - mu) * rstd * wb.z + bb.z;
    float n7 = (x1.w - mu) * rstd * wb.w + bb.w;

    uint4 on; on.x = pk_bf2(n0,n1); on.y = pk_bf2(n2,n3); on.z = pk_bf2(n4,n5); on.w = pk_bf2(n6,n7);
    uint4 oq; oq.x = pk_bf2(n0+p0.x, n1+p0.y); oq.y = pk_bf2(n2+p0.z, n3+p0.w);
    oq.z = pk_bf2(n4+p1.x, n5+p1.y); oq.w = pk_bf2(n6+p1.z, n7+p1.w);

    __nv_bfloat16* vn  = (__nv_bfloat16*)(g_scratch + OFF_VN);
    __nv_bfloat16* qin = (__nv_bfloat16*)(g_scratch + OFF_QIN);
    *reinterpret_cast<uint4*>(vn  + (size_t)row * KVD + lane * 8) = on;
    *reinterpret_cast<uint4*>(qin + (size_t)row * KVD + lane * 8) = oq;
}

// ---------------- LayerNorm(l): one block per 768-wide row ----------------
__global__ __launch_bounds__(256) void lnl_kernel(const float* __restrict__ l,
                                                  const float* __restrict__ w,
                                                  const float* __restrict__ b) {
    int row = blockIdx.x, tid = threadIdx.x;
    const float* lr = l + (size_t)row * KLD;
    float x0 = lr[tid], x1 = lr[tid + 256], x2 = lr[tid + 512];
    float s = x0 + x1 + x2;
    float q = x0*x0 + x1*x1 + x2*x2;
    #pragma unroll
    for (int o = 16; o > 0; o >>= 1) {
        s += __shfl_xor_sync(0xffffffffu, s, o);
        q += __shfl_xor_sync(0xffffffffu, q, o);
    }
    __shared__ float rs[8], rq[8];
    if ((tid & 31) == 0) { rs[tid >> 5] = s; rq[tid >> 5] = q; }
    __syncthreads();
    float S = 0.f, Q = 0.f;
    #pragma unroll
    for (int i = 0; i < 8; i++) { S += rs[i]; Q += rq[i]; }
    float mu = S * (1.0f / KLD);
    float var = Q * (1.0f / KLD) - mu * mu;
    float rstd = rsqrtf(var + 1e-5f);
    __nv_bfloat16* out = (__nv_bfloat16*)(g_scratch + OFF_LN) + (size_t)row * KLD;
    out[tid]       = __float2bfloat16((x0 - mu) * rstd * w[tid]       + b[tid]);
    out[tid + 256] = __float2bfloat16((x1 - mu) * rstd * w[tid + 256] + b[tid + 256]);
    out[tid + 512] = __float2bfloat16((x2 - mu) * rstd * w[tid + 512] + b[tid + 512]);
}

// ---------------- generic bf16 wmma GEMM: C = A[M,K] @ B[K,N] ----------------
// epilogue: outb != null:  outb = bf16((acc + bias[n]) * alpha)
//           else:          outf = resid + gamma[n] * (acc + bias[n])
#define GBM 128
#define GBN 64
#define GBK 64
__global__ __launch_bounds__(256) void gemm_kernel(
    const __nv_bfloat16* __restrict__ A, const __nv_bfloat16* __restrict__ Bm,
    const float* __restrict__ bias, float alpha,
    const float* __restrict__ resid, const float* __restrict__ gamma,
    __nv_bfloat16* __restrict__ outb, float* __restrict__ outf,
    int M, int N, int K)
{
    __shared__ __align__(16) unsigned char smem_raw[34816];
    __nv_bfloat16* As = (__nv_bfloat16*)smem_raw;              // 128 x 72
    __nv_bfloat16* Bs = (__nv_bfloat16*)(smem_raw + 18432);    // 64 x 72
    float* Cs = (float*)smem_raw;                              // 128 x 68

    const int tid = threadIdx.x;
    const int wid = tid >> 5;
    const int m0 = blockIdx.y * GBM;
    const int n0 = blockIdx.x * GBN;
    const int wm = wid & 3, wn = wid >> 2;

    wmma::fragment<wmma::accumulator, 16, 16, 16, float> c[2][2];
    #pragma unroll
    for (int i = 0; i < 2; i++)
        #pragma unroll
        for (int j = 0; j < 2; j++) wmma::fill_fragment(c[i][j], 0.0f);

    for (int k0 = 0; k0 < K; k0 += GBK) {
        #pragma unroll
        for (int j = 0; j < 4; j++) {
            int u = tid + j * 256;
            int r = u >> 3, cc = (u & 7) << 3;
            *reinterpret_cast<uint4*>(As + r * 72 + cc) =
                *reinterpret_cast<const uint4*>(A + (size_t)(m0 + r) * K + k0 + cc);
        }
        #pragma unroll
        for (int j = 0; j < 2; j++) {
            int u = tid + j * 256;
            int r = u >> 3, cc = (u & 7) << 3;
            *reinterpret_cast<uint4*>(Bs + r * 72 + cc) =
                *reinterpret_cast<const uint4*>(Bm + (size_t)(k0 + r) * N + n0 + cc);
        }
        __syncthreads();
        #pragma unroll
        for (int ks = 0; ks < 4; ks++) {
            wmma::fragment<wmma::matrix_a, 16, 16, 16, __nv_bfloat16, wmma::row_major> af[2];
            wmma::fragment<wmma::matrix_b, 16, 16, 16, __nv_bfloat16, wmma::row_major> bf[2];
            #pragma unroll
            for (int i = 0; i < 2; i++)
                wmma::load_matrix_sync(af[i], As + (wm * 32 + i * 16) * 72 + ks * 16, 72);
            #pragma unroll
            for (int j = 0; j < 2; j++)
                wmma::load_matrix_sync(bf[j], Bs + (ks * 16) * 72 + wn * 32 + j * 16, 72);
            #pragma unroll
            for (int i = 0; i < 2; i++)
                #pragma unroll
                for (int j = 0; j < 2; j++)
                    wmma::mma_sync(c[i][j], af[i], bf[j], c[i][j]);
        }
        __syncthreads();
    }
    #pragma unroll
    for (int i = 0; i < 2; i++)
        #pragma unroll
        for (int j = 0; j < 2; j++)
            wmma::store_matrix_sync(Cs + (wm * 32 + i * 16) * 68 + wn * 32 + j * 16,
                                    c[i][j], 68, wmma::mem_row_major);
    __syncthreads();
    #pragma unroll 8
    for (int j = 0; j < 32; j++) {
        int u = tid + j * 256;
        int r = u >> 6, cc = u & 63;
        int gm = m0 + r, gn = n0 + cc;
        float val = Cs[r * 68 + cc] + bias[gn];
        if (outb) {
            outb[(size_t)gm * N + gn] = __float2bfloat16(val * alpha);
        } else {
            outf[(size_t)gm * N + gn] = resid[(size_t)gm * N + gn] + gamma[gn] * val;
        }
    }
}

// ---------------- fused bidirectional attention ----------------
// grid: B*H*NSPLIT blocks, 128 threads (4 warps). Each block: one (b,h), T-chunk of 1024.
// Per 64-row tile: S = q@k^T, e = exp(S), p_v = e/rowsum, out_v = p_v@vl,
// U += e^T@vv (persistent wmma accum), Z += colsum(e).
#define NSPLIT 8
#define ROWS_PB (KT / NSPLIT)   /* 1024 */
#define NTILES  (ROWS_PB / 64)  /* 16   */
#define ATT_SMEM 54528

__global__ __launch_bounds__(128) void attn_kernel() {
    extern __shared__ char dyn[];
    __nv_bfloat16* ks_ = (__nv_bfloat16*)(dyn);             // k  [64 x 72]
    __nv_bfloat16* vls = (__nv_bfloat16*)(dyn + 9216);      // vl [64 x 72]
    __nv_bfloat16* qs  = (__nv_bfloat16*)(dyn + 18432);     // q tile / e tile (aliased)
    __nv_bfloat16* vvs = (__nv_bfloat16*)(dyn + 27648);     // vv tile
    float*         Sf  = (float*)(dyn + 36864);             // logits/exp/O staging [64 x 68]
    float*         inv = (float*)(dyn + 54272);             // 1/rowsum [64]

    const __nv_bfloat16* qg  = (const __nv_bfloat16*)(g_scratch + OFF_Q);
    const __nv_bfloat16* vvg = (const __nv_bfloat16*)(g_scratch + OFF_VV);
    const __nv_bfloat16* kg  = (const __nv_bfloat16*)(g_scratch + OFF_K);
    const __nv_bfloat16* vlg = (const __nv_bfloat16*)(g_scratch + OFF_VL);
    __nv_bfloat16* ovg = (__nv_bfloat16*)(g_scratch + OFF_OV);
    float* Ug = (float*)(g_scratch + OFF_U);
    float* Zg = (float*)(g_scratch + OFF_Z);

    const int bid = blockIdx.x;
    const int sp  = bid & (NSPLIT - 1);
    const int h   = (bid / NSPLIT) & (KH - 1);
    const int b   = bid / (NSPLIT * KH);
    const int tid = threadIdx.x, wid = tid >> 5;

    // preload k, vl [64 rows x 64 cols] for this (b,h)
    #pragma unroll
    for (int j = 0; j < 4; j++) {
        int u = tid + j * 128;
        int r = u >> 3, cc = (u & 7) << 3;
        size_t g = (size_t)(b * KS + r) * KE + h * 64 + cc;
        *reinterpret_cast<uint4*>(ks_ + r * 72 + cc) = *reinterpret_cast<const uint4*>(kg + g);
        *reinterpret_cast<uint4*>(vls + r * 72 + cc) = *reinterpret_cast<const uint4*>(vlg + g);
    }

    wmma::fragment<wmma::accumulator, 16, 16, 16, float> cU[4];
    #pragma unroll
    for (int j = 0; j < 4; j++) wmma::fill_fragment(cU[j], 0.0f);
    float Zreg = 0.0f;
    __syncthreads();

    for (int t = 0; t < NTILES; t++) {
        const int row0 = sp * ROWS_PB + t * 64;
        // load q, vv tiles
        #pragma unroll
        for (int j = 0; j < 4; j++) {
            int u = tid + j * 128;
            int r = u >> 3, cc = (u & 7) << 3;
            size_t g = (size_t)(b * KT + row0 + r) * KE + h * 64 + cc;
            *reinterpret_cast<uint4*>(qs  + r * 72 + cc) = *reinterpret_cast<const uint4*>(qg  + g);
            *reinterpret_cast<uint4*>(vvs + r * 72 + cc) = *reinterpret_cast<const uint4*>(vvg + g);
        }
        __syncthreads();
        // S = q @ k^T   (warp owns 16 t-rows x 64 s-cols)
        {
            wmma::fragment<wmma::accumulator, 16, 16, 16, float> cS[4];
            #pragma unroll
            for (int j = 0; j < 4; j++) wmma::fill_fragment(cS[j], 0.0f);
            #pragma unroll
            for (int kd = 0; kd < 4; kd++) {
                wmma::fragment<wmma::matrix_a, 16, 16, 16, __nv_bfloat16, wmma::row_major> af;
                wmma::load_matrix_sync(af, qs + wid * 16 * 72 + kd * 16, 72);
                #pragma unroll
                for (int j = 0; j < 4; j++) {
                    wmma::fragment<wmma::matrix_b, 16, 16, 16, __nv_bfloat16, wmma::col_major> bf;
                    wmma::load_matrix_sync(bf, ks_ + kd * 16 + j * 16 * 72, 72);
                    wmma::mma_sync(cS[j], af, bf, cS[j]);
                }
            }
            #pragma unroll
            for (int j = 0; j < 4; j++)
                wmma::store_matrix_sync(Sf + wid * 16 * 68 + j * 16, cS[j], 68, wmma::mem_row_major);
        }
        __syncthreads();
        // exp: fp32 back into Sf, bf16 into es (= qs)
        #pragma unroll 8
        for (int j = 0; j < 32; j++) {
            int u = tid + j * 128;
            int r = u >> 6, s2 = u & 63;
            float e = __expf(Sf[r * 68 + s2]);
            Sf[r * 68 + s2] = e;
            qs[r * 72 + s2] = __float2bfloat16(e);
        }
        __syncthreads();
        // sums: lower half -> rowsum (p_v), upper half -> colsum (Z for p_l)
        if (tid < 64) {
            float rsum = 0.0f;
            #pragma unroll 8
            for (int s2 = 0; s2 < 64; s2++) rsum += Sf[tid * 68 + s2];
            inv[tid] = 1.0f / rsum;
        } else {
            int s2 = tid - 64;
            float cz = 0.0f;
            #pragma unroll 8
            for (int r = 0; r < 64; r++) cz += Sf[r * 68 + s2];
            Zreg += cz;
        }
        __syncthreads();
        // O = e @ vl (staged into Sf), U += e^T @ vv (persistent)
        {
            wmma::fragment<wmma::accumulator, 16, 16, 16, float> cO[4];
            #pragma unroll
            for (int j = 0; j < 4; j++) wmma::fill_fragment(cO[j], 0.0f);
            #pragma unroll
            for (int ks2 = 0; ks2 < 4; ks2++) {
                wmma::fragment<wmma::matrix_a, 16, 16, 16, __nv_bfloat16, wmma::row_major> af;
                wmma::load_matrix_sync(af, qs + wid * 16 * 72 + ks2 * 16, 72);
                #pragma unroll
                for (int j = 0; j < 4; j++) {
                    wmma::fragment<wmma::matrix_b, 16, 16, 16, __nv_bfloat16, wmma::row_major> bf;
                    wmma::load_matrix_sync(bf, vls + ks2 * 16 * 72 + j * 16, 72);
                    wmma::mma_sync(cO[j], af, bf, cO[j]);
                }
            }
            #pragma unroll
            for (int kt2 = 0; kt2 < 4; kt2++) {
                wmma::fragment<wmma::matrix_a, 16, 16, 16, __nv_bfloat16, wmma::col_major> af;  // e^T
                wmma::load_matrix_sync(af, qs + wid * 16 + kt2 * 16 * 72, 72);
                #pragma unroll
                for (int j = 0; j < 4; j++) {
                    wmma::fragment<wmma::matrix_b, 16, 16, 16, __nv_bfloat16, wmma::row_major> bf;
                    wmma::load_matrix_sync(bf, vvs + kt2 * 16 * 72 + j * 16, 72);
                    wmma::mma_sync(cU[j], af, bf, cU[j]);
                }
            }
            #pragma unroll
            for (int j = 0; j < 4; j++)
                wmma::store_matrix_sync(Sf + wid * 16 * 68 + j * 16, cO[j], 68, wmma::mem_row_major);
        }
        __syncthreads();
        // write out_v = O / rowsum, bf16, head-interleaved [t, h*64+d]
        #pragma unroll
        for (int j = 0; j < 4; j++) {
            int u = tid + j * 128;
            int r = u >> 3, cc = (u & 7) << 3;
            float vi = inv[r];
            uint4 o;
            o.x = pk_bf2(Sf[r * 68 + cc + 0] * vi, Sf[r * 68 + cc + 1] * vi);
            o.y = pk_bf2(Sf[r * 68 + cc + 2] * vi, Sf[r * 68 + cc + 3] * vi);
            o.z = pk_bf2(Sf[r * 68 + cc + 4] * vi, Sf[r * 68 + cc + 5] * vi);
            o.w = pk_bf2(Sf[r * 68 + cc + 6] * vi, Sf[r * 68 + cc + 7] * vi);
            *reinterpret_cast<uint4*>(ovg + (size_t)(b * KT + row0 + r) * KE + h * 64 + cc) = o;
        }
        __syncthreads();
    }
    // flush U and Z
    #pragma unroll
    for (int j = 0; j < 4; j++)
        wmma::store_matrix_sync(Sf + wid * 16 * 68 + j * 16, cU[j], 68, wmma::mem_row_major);
    __syncthreads();
    #pragma unroll 4
    for (int j = 0; j < 32; j++) {
        int u = tid + j * 128;
        int s2 = u >> 6, d = u & 63;
        atomicAdd(&Ug[(((size_t)b * KH + h) * KS + s2) * KHD + d], Sf[s2 * 68 + d]);
    }
    if (tid >= 64) atomicAdd(&Zg[((size_t)b * KH + h) * KS + (tid - 64)], Zreg);
}

// ---------------- merge: out_l = U/Z -> head-merged bf16 [512,1024] ----------------
__global__ void merge_kernel() {
    int i = blockIdx.x * 256 + threadIdx.x;   // over B*H*S*D = 524288
    const float* Ug = (const float*)(g_scratch + OFF_U);
    const float* Zg = (const float*)(g_scratch + OFF_Z);
    __nv_bfloat16* mg = (__nv_bfloat16*)(g_scratch + OFF_MG);
    int d = i & 63, s = (i >> 6) & 63, h = (i >> 12) & 15, b = i >> 16;
    float val = Ug[i] / Zg[i >> 6];
    mg[(size_t)(b * KS + s) * KE + h * 64 + d] = __float2bfloat16(val);
}

// ---------------- launch ----------------
extern "C" void kernel_launch(void* const* d_in, const int* in_sizes, int n_in,
                              void* d_out, int out_size) {
    (void)in_sizes; (void)n_in; (void)out_size;
    const float* v    = (const float*)d_in[0];
    const float* l    = (const float*)d_in[1];
    const float* vpos = (const float*)d_in[2];
    const float* lnvw = (const float*)d_in[3];
    const float* lnvb = (const float*)d_in[4];
    const float* lnlw = (const float*)d_in[5];
    const float* lnlb = (const float*)d_in[6];
    const float* wq   = (const float*)d_in[7];
    const float* bq   = (const float*)d_in[8];
    const float* wk   = (const float*)d_in[9];
    const float* bk   = (const float*)d_in[10];
    const float* wvv  = (const float*)d_in[11];
    const float* bvv  = (const float*)d_in[12];
    const float* wvl  = (const float*)d_in[13];
    const float* bvl  = (const float*)d_in[14];
    const float* wov  = (const float*)d_in[15];
    const float* bov  = (const float*)d_in[16];
    const float* wol  = (const float*)d_in[17];
    const float* bol  = (const float*)d_in[18];
    const float* gv   = (const float*)d_in[19];
    const float* gl   = (const float*)d_in[20];
    float* outv = (float*)d_out;
    float* outl = outv + (size_t)KMV * KVD;

    unsigned char* base = nullptr;
    cudaGetSymbolAddress((void**)&base, g_scratch);
    cudaFuncSetAttribute(attn_kernel, cudaFuncAttributeMaxDynamicSharedMemorySize, ATT_SMEM);

    // zero U/Z accumulators (scratch persists across graph replays)
    zero_kernel<<<2080, 256>>>();

    // weights -> bf16
    cvt_kernel<<<1024, 256>>>(wq,  (__nv_bfloat16*)(base + OFF_WQ),  262144);
    cvt_kernel<<<1024, 256>>>(wvv, (__nv_bfloat16*)(base + OFF_WVV), 262144);
    cvt_kernel<<<1024, 256>>>(wov, (__nv_bfloat16*)(base + OFF_WOV), 262144);
    cvt_kernel<<<3072, 256>>>(wk,  (__nv_bfloat16*)(base + OFF_WK),  786432);
    cvt_kernel<<<3072, 256>>>(wvl, (__nv_bfloat16*)(base + OFF_WVL), 786432);
    cvt_kernel<<<3072, 256>>>(wol, (__nv_bfloat16*)(base + OFF_WOL), 786432);

    // layernorms
    lnl_kernel<<<KML, 256>>>(l, lnlw, lnlb);
    lnv_kernel<<<KMV / 8, 256>>>(v, vpos, lnvw, lnvb);

    // projections
    gemm_kernel<<<dim3(KE / GBN, KMV / GBM), 256>>>(
        (__nv_bfloat16*)(base + OFF_QIN), (__nv_bfloat16*)(base + OFF_WQ),
        bq, QK_SCALE, nullptr, nullptr,
        (__nv_bfloat16*)(base + OFF_Q), nullptr, KMV, KE, KVD);
    gemm_kernel<<<dim3(KE / GBN, KMV / GBM), 256>>>(
        (__nv_bfloat16*)(base + OFF_VN), (__nv_bfloat16*)(base + OFF_WVV),
        bvv, 1.0f, nullptr, nullptr,
        (__nv_bfloat16*)(base + OFF_VV), nullptr, KMV, KE, KVD);
    gemm_kernel<<<dim3(KE / GBN, KML / GBM), 256>>>(
        (__nv_bfloat16*)(base + OFF_LN), (__nv_bfloat16*)(base + OFF_WK),
        bk, 1.0f, nullptr, nullptr,
        (__nv_bfloat16*)(base + OFF_K), nullptr, KML, KE, KLD);
    gemm_kernel<<<dim3(KE / GBN, KML / GBM), 256>>>(
        (__nv_bfloat16*)(base + OFF_LN), (__nv_bfloat16*)(base + OFF_WVL),
        bvl, 1.0f, nullptr, nullptr,
        (__nv_bfloat16*)(base + OFF_VL), nullptr, KML, KE, KLD);

    // fused bidirectional attention
    attn_kernel<<<KB * KH * NSPLIT, 128, ATT_SMEM>>>();

    // l-side merge + output projections with gated residual
    merge_kernel<<<2048, 256>>>();
    gemm_kernel<<<dim3(KVD / GBN, KMV / GBM), 256>>>(
        (__nv_bfloat16*)(base + OFF_OV), (__nv_bfloat16*)(base + OFF_WOV),
        bov, 1.0f, v, gv, nullptr, outv, KMV, KVD, KE);
    gemm_kernel<<<dim3(KLD / GBN, KML / GBM), 256>>>(
        (__nv_bfloat16*)(base + OFF_MG), (__nv_bfloat16*)(base + OFF_WOL),
        bol, 1.0f, l, gl, nullptr, outl, KML, KLD, KE);
}

// round 6
// speedup vs baseline: 1.0571x; 1.0571x over previous
#include <cuda_runtime.h>
#include <cuda_bf16.h>
#include <mma.h>
#include <cstdint>
#include <cstddef>

using namespace nvcuda;

// ---------------- problem constants ----------------
#define KB     8
#define KT     8192
#define KS     64
#define KVD    256
#define KLD    768
#define KE     1024
#define KH     16
#define KHD    64
#define KMV    (KB*KT)     /* 65536 */
#define KML    (KB*KS)     /* 512   */
#define QK_SCALE 0.125f

// ---------------- scratch layout (single __device__ arena) ----------------
#define OFF_VN   ((size_t)0)                      /* [65536,256] bf16 */
#define OFF_QIN  ((size_t)33554432)               /* [65536,256] bf16 */
#define OFF_Q    ((size_t)67108864)               /* [65536,1024] bf16 */
#define OFF_VV   ((size_t)201326592)              /* [65536,1024] bf16 */
#define OFF_OV   ((size_t)335544320)              /* [65536,1024] bf16 */
#define OFF_LN   ((size_t)469762048)              /* [512,768] bf16 */
#define OFF_K    ((size_t)470548480)              /* [512,1024] bf16 */
#define OFF_VL   ((size_t)471597056)              /* [512,1024] bf16 */
#define OFF_MG   ((size_t)472645632)              /* [512,1024] bf16 */
#define OFF_U    ((size_t)473694208)              /* [8,16,64,64] f32 */
#define OFF_Z    ((size_t)475791360)              /* [8,16,64] f32 */
#define OFF_WQ   ((size_t)475824128)              /* [256,1024] bf16 */
#define OFF_WVV  ((size_t)476348416)              /* [256,1024] bf16 */
#define OFF_WOV  ((size_t)476872704)              /* [1024,256] bf16 */
#define OFF_WK   ((size_t)477396992)              /* [768,1024] bf16 */
#define OFF_WVL  ((size_t)478969856)              /* [768,1024] bf16 */
#define OFF_WOL  ((size_t)480542720)              /* [1024,768] bf16 */
#define SCRATCH_BYTES ((size_t)482115584)

__device__ __align__(256) unsigned char g_scratch[SCRATCH_BYTES];

// ---------------- helpers ----------------
__device__ __forceinline__ uint32_t pk_bf2(float a, float b) {
    __nv_bfloat162 t = __floats2bfloat162_rn(a, b);
    return *reinterpret_cast<uint32_t*>(&t);
}
__device__ __forceinline__ uint32_t smem_u32(const void* p) {
    uint32_t a;
    asm("{ .reg .u64 t; cvta.to.shared.u64 t, %1; cvt.u32.u64 %0, t; }" : "=r"(a) : "l"(p));
    return a;
}
__device__ __forceinline__ void cp16(uint32_t dst, const void* src) {
    asm volatile("cp.async.cg.shared.global [%0], [%1], 16;\n" :: "r"(dst), "l"(src));
}
__device__ __forceinline__ void cp_commit() {
    asm volatile("cp.async.commit_group;\n" ::);
}

// ---------------- zero U/Z ----------------
__global__ void zero_kernel() {
    size_t i = (size_t)blockIdx.x * 256 + threadIdx.x;
    const size_t n = (size_t)KB*KH*KS*KHD + (size_t)KB*KH*KS;
    float* p = (float*)(g_scratch + OFF_U);
    if (i < n) p[i] = 0.0f;
}

// ---------------- fp32 -> bf16 convert ----------------
__global__ void cvt_kernel(const float* __restrict__ s, __nv_bfloat16* __restrict__ d, int n) {
    int i = blockIdx.x * 256 + threadIdx.x;
    if (i < n) d[i] = __float2bfloat16(s[i]);
}

// ---------------- LayerNorm(v) + v_pos ----------------
__global__ __launch_bounds__(256) void lnv_kernel(const float* __restrict__ v,
                                                  const float* __restrict__ vp,
                                                  const float* __restrict__ w,
                                                  const float* __restrict__ b) {
    int row  = blockIdx.x * 8 + (threadIdx.x >> 5);
    int lane = threadIdx.x & 31;
    const float4* vr = reinterpret_cast<const float4*>(v + (size_t)row * KVD) + lane * 2;
    float4 x0 = vr[0], x1 = vr[1];
    float s = x0.x + x0.y + x0.z + x0.w + x1.x + x1.y + x1.z + x1.w;
    float q = x0.x*x0.x + x0.y*x0.y + x0.z*x0.z + x0.w*x0.w
            + x1.x*x1.x + x1.y*x1.y + x1.z*x1.z + x1.w*x1.w;
    #pragma unroll
    for (int o = 16; o > 0; o >>= 1) {
        s += __shfl_xor_sync(0xffffffffu, s, o);
        q += __shfl_xor_sync(0xffffffffu, q, o);
    }
    float mu   = s * (1.0f / KVD);
    float var  = q * (1.0f / KVD) - mu * mu;
    float rstd = rsqrtf(var + 1e-5f);

    const float4* vpr = reinterpret_cast<const float4*>(vp + (size_t)row * KVD) + lane * 2;
    float4 p0 = vpr[0], p1 = vpr[1];
    const float4* w4 = reinterpret_cast<const float4*>(w) + lane * 2;
    const float4* b4 = reinterpret_cast<const float4*>(b) + lane * 2;
    float4 wa = w4[0], wb = w4[1], ba = b4[0], bb = b4[1];

    float n0 = (x0.x - mu) * rstd * wa.x + ba.x;
    float n1 = (x0.y - mu) * rstd * wa.y + ba.y;
    float n2 = (x0.z - mu) * rstd * wa.z + ba.z;
    float n3 = (x0.w - mu) * rstd * wa.w + ba.w;
    float n4 = (x1.x - mu) * rstd * wb.x + bb.x;
    float n5 = (x1.y - mu) * rstd * wb.y + bb.y;
    float n6 = (x1.z - mu) * rstd * wb.z + bb.z;
    float n7 = (x1.w - mu) * rstd * wb.w + bb.w;

    uint4 on; on.x = pk_bf2(n0,n1); on.y = pk_bf2(n2,n3); on.z = pk_bf2(n4,n5); on.w = pk_bf2(n6,n7);
    uint4 oq; oq.x = pk_bf2(n0+p0.x, n1+p0.y); oq.y = pk_bf2(n2+p0.z, n3+p0.w);
    oq.z = pk_bf2(n4+p1.x, n5+p1.y); oq.w = pk_bf2(n6+p1.z, n7+p1.w);

    __nv_bfloat16* vn  = (__nv_bfloat16*)(g_scratch + OFF_VN);
    __nv_bfloat16* qin = (__nv_bfloat16*)(g_scratch + OFF_QIN);
    *reinterpret_cast<uint4*>(vn  + (size_t)row * KVD + lane * 8) = on;
    *reinterpret_cast<uint4*>(qin + (size_t)row * KVD + lane * 8) = oq;
}

// ---------------- LayerNorm(l) ----------------
__global__ __launch_bounds__(256) void lnl_kernel(const float* __restrict__ l,
                                                  const float* __restrict__ w,
                                                  const float* __restrict__ b) {
    int row = blockIdx.x, tid = threadIdx.x;
    const float* lr = l + (size_t)row * KLD;
    float x0 = lr[tid], x1 = lr[tid + 256], x2 = lr[tid + 512];
    float s = x0 + x1 + x2;
    float q = x0*x0 + x1*x1 + x2*x2;
    #pragma unroll
    for (int o = 16; o > 0; o >>= 1) {
        s += __shfl_xor_sync(0xffffffffu, s, o);
        q += __shfl_xor_sync(0xffffffffu, q, o);
    }
    __shared__ float rs[8], rq[8];
    if ((tid & 31) == 0) { rs[tid >> 5] = s; rq[tid >> 5] = q; }
    __syncthreads();
    float S = 0.f, Q = 0.f;
    #pragma unroll
    for (int i = 0; i < 8; i++) { S += rs[i]; Q += rq[i]; }
    float mu = S * (1.0f / KLD);
    float var = Q * (1.0f / KLD) - mu * mu;
    float rstd = rsqrtf(var + 1e-5f);
    __nv_bfloat16* out = (__nv_bfloat16*)(g_scratch + OFF_LN) + (size_t)row * KLD;
    out[tid]       = __float2bfloat16((x0 - mu) * rstd * w[tid]       + b[tid]);
    out[tid + 256] = __float2bfloat16((x1 - mu) * rstd * w[tid + 256] + b[tid + 256]);
    out[tid + 512] = __float2bfloat16((x2 - mu) * rstd * w[tid + 512] + b[tid + 512]);
}

// ============================================================================
// Pipelined GEMM: C[M,N] = A[M,K] @ B[K,N], bf16 in, fp32 accum.
// 128x128 CTA tile, K-chunks of 64, cp.async double-buffered, 8 warps
// with 64x32 warp tiles. Epilogue: outb=bf16((acc+bias)*alpha) or
// outf = resid + gamma*(acc+bias).
// ============================================================================
#define PG_STAGE 35840          /* A 128x72x2 = 18432 + B 64x136x2 = 17408 */
#define PG_SMEM  (2 * PG_STAGE) /* 71680 */

__global__ __launch_bounds__(256) void pgemm_kernel(
    const __nv_bfloat16* __restrict__ A, const __nv_bfloat16* __restrict__ Bm,
    const float* __restrict__ bias, float alpha,
    const float* __restrict__ resid, const float* __restrict__ gamma,
    __nv_bfloat16* __restrict__ outb, float* __restrict__ outf,
    int M, int N, int K)
{
    extern __shared__ __align__(16) char ps[];
    const uint32_t sb = smem_u32(ps);
    const int tid = threadIdx.x, wid = tid >> 5;
    const int m0 = blockIdx.y * 128, n0 = blockIdx.x * 128;
    const int wm = wid >> 2, wn = wid & 3;   // 2 x 4 warps; warp tile 64m x 32n

    wmma::fragment<wmma::accumulator, 16, 16, 16, float> acc[4][2];
    #pragma unroll
    for (int i = 0; i < 4; i++)
        #pragma unroll
        for (int j = 0; j < 2; j++) wmma::fill_fragment(acc[i][j], 0.0f);

    const int NK = K >> 6;

    // prefetch helper is inlined manually (stage s, chunk kc)
    {   // prefetch chunk 0 into stage 0
        const __nv_bfloat16* Ag = A + (size_t)m0 * K;
        const __nv_bfloat16* Bg = Bm + n0;
        uint32_t ab = sb, bb = sb + 18432;
        #pragma unroll
        for (int j = 0; j < 4; j++) {
            int u = tid + j * 256; int r = u >> 3, c8 = (u & 7) << 3;
            cp16(ab + (uint32_t)(r * 72 + c8) * 2, Ag + (size_t)r * K + c8);
        }
        #pragma unroll
        for (int j = 0; j < 4; j++) {
            int u = tid + j * 256; int r = u >> 4, c8 = (u & 15) << 3;
            cp16(bb + (uint32_t)(r * 136 + c8) * 2, Bg + (size_t)r * N + c8);
        }
        cp_commit();
    }

    for (int kc = 0; kc < NK; kc++) {
        if (kc + 1 < NK) {
            const int st = (kc + 1) & 1;
            const __nv_bfloat16* Ag = A + (size_t)m0 * K + (kc + 1) * 64;
            const __nv_bfloat16* Bg = Bm + (size_t)((kc + 1) * 64) * N + n0;
            uint32_t ab = sb + st * PG_STAGE, bb = ab + 18432;
            #pragma unroll
            for (int j = 0; j < 4; j++) {
                int u = tid + j * 256; int r = u >> 3, c8 = (u & 7) << 3;
                cp16(ab + (uint32_t)(r * 72 + c8) * 2, Ag + (size_t)r * K + c8);
            }
            #pragma unroll
            for (int j = 0; j < 4; j++) {
                int u = tid + j * 256; int r = u >> 4, c8 = (u & 15) << 3;
                cp16(bb + (uint32_t)(r * 136 + c8) * 2, Bg + (size_t)r * N + c8);
            }
            cp_commit();
            asm volatile("cp.async.wait_group 1;\n" ::);
        } else {
            asm volatile("cp.async.wait_group 0;\n" ::);
        }
        __syncthreads();

        const __nv_bfloat16* As = (const __nv_bfloat16*)(ps + (kc & 1) * PG_STAGE);
        const __nv_bfloat16* Bs = (const __nv_bfloat16*)(ps + (kc & 1) * PG_STAGE + 18432);
        #pragma unroll
        for (int ks = 0; ks < 4; ks++) {
            wmma::fragment<wmma::matrix_a, 16, 16, 16, __nv_bfloat16, wmma::row_major> af[4];
            wmma::fragment<wmma::matrix_b, 16, 16, 16, __nv_bfloat16, wmma::row_major> bf[2];
            #pragma unroll
            for (int i = 0; i < 4; i++)
                wmma::load_matrix_sync(af[i], As + (wm * 64 + i * 16) * 72 + ks * 16, 72);
            #pragma unroll
            for (int j = 0; j < 2; j++)
                wmma::load_matrix_sync(bf[j], Bs + (ks * 16) * 136 + wn * 32 + j * 16, 136);
            #pragma unroll
            for (int i = 0; i < 4; i++)
                #pragma unroll
                for (int j = 0; j < 2; j++)
                    wmma::mma_sync(acc[i][j], af[i], bf[j], acc[i][j]);
        }
        __syncthreads();
    }

    // ---- epilogue: stage accumulators in smem (stride 132 fp32), then write
    float* Cs = (float*)ps;
    #pragma unroll
    for (int i = 0; i < 4; i++)
        #pragma unroll
        for (int j = 0; j < 2; j++)
            wmma::store_matrix_sync(Cs + (wm * 64 + i * 16) * 132 + wn * 32 + j * 16,
                                    acc[i][j], 132, wmma::mem_row_major);
    __syncthreads();

    // 128 rows x 16 chunks of 8 cols = 2048 units, 8 per thread
    if (outb) {
        #pragma unroll
        for (int j = 0; j < 8; j++) {
            int u = tid + j * 256;
            int r = u >> 4, c8 = (u & 15) << 3;
            int gm = m0 + r, gc = n0 + c8;
            uint32_t pk[4];
            #pragma unroll
            for (int i = 0; i < 4; i++) {
                float a0 = (Cs[r * 132 + c8 + 2*i]     + bias[gc + 2*i])     * alpha;
                float a1 = (Cs[r * 132 + c8 + 2*i + 1] + bias[gc + 2*i + 1]) * alpha;
                pk[i] = pk_bf2(a0, a1);
            }
            *reinterpret_cast<uint4*>(outb + (size_t)gm * N + gc) =
                make_uint4(pk[0], pk[1], pk[2], pk[3]);
        }
    } else {
        #pragma unroll
        for (int j = 0; j < 8; j++) {
            int u = tid + j * 256;
            int r = u >> 4, c8 = (u & 15) << 3;
            int gm = m0 + r, gc = n0 + c8;
            const float4* rsd = reinterpret_cast<const float4*>(resid + (size_t)gm * N + gc);
            float4* dst = reinterpret_cast<float4*>(outf + (size_t)gm * N + gc);
            #pragma unroll
            for (int i = 0; i < 2; i++) {
                float4 rv = rsd[i];
                float4 o;
                o.x = rv.x + gamma[gc + 4*i + 0] * (Cs[r * 132 + c8 + 4*i + 0] + bias[gc + 4*i + 0]);
                o.y = rv.y + gamma[gc + 4*i + 1] * (Cs[r * 132 + c8 + 4*i + 1] + bias[gc + 4*i + 1]);
                o.z = rv.z + gamma[gc + 4*i + 2] * (Cs[r * 132 + c8 + 4*i + 2] + bias[gc + 4*i + 2]);
                o.w = rv.w + gamma[gc + 4*i + 3] * (Cs[r * 132 + c8 + 4*i + 3] + bias[gc + 4*i + 3]);
                dst[i] = o;
            }
        }
    }
}

// ---------------- wmma GEMM (small l-side GEMMs only) ----------------
#define GBM 128
#define GBN 64
#define GBK 64
__global__ __launch_bounds__(256) void gemm_kernel(
    const __nv_bfloat16* __restrict__ A, const __nv_bfloat16* __restrict__ Bm,
    const float* __restrict__ bias, float alpha,
    const float* __restrict__ resid, const float* __restrict__ gamma,
    __nv_bfloat16* __restrict__ outb, float* __restrict__ outf,
    int M, int N, int K)
{
    __shared__ __align__(16) unsigned char smem_raw[34816];
    __nv_bfloat16* As = (__nv_bfloat16*)smem_raw;              // 128 x 72
    __nv_bfloat16* Bs = (__nv_bfloat16*)(smem_raw + 18432);    // 64 x 72
    float* Cs = (float*)smem_raw;                              // 128 x 68

    const int tid = threadIdx.x;
    const int wid = tid >> 5;
    const int m0 = blockIdx.y * GBM;
    const int n0 = blockIdx.x * GBN;
    const int wm = wid & 3, wn = wid >> 2;

    wmma::fragment<wmma::accumulator, 16, 16, 16, float> c[2][2];
    #pragma unroll
    for (int i = 0; i < 2; i++)
        #pragma unroll
        for (int j = 0; j < 2; j++) wmma::fill_fragment(c[i][j], 0.0f);

    for (int k0 = 0; k0 < K; k0 += GBK) {
        #pragma unroll
        for (int j = 0; j < 4; j++) {
            int u = tid + j * 256;
            int r = u >> 3, cc = (u & 7) << 3;
            *reinterpret_cast<uint4*>(As + r * 72 + cc) =
                *reinterpret_cast<const uint4*>(A + (size_t)(m0 + r) * K + k0 + cc);
        }
        #pragma unroll
        for (int j = 0; j < 2; j++) {
            int u = tid + j * 256;
            int r = u >> 3, cc = (u & 7) << 3;
            *reinterpret_cast<uint4*>(Bs + r * 72 + cc) =
                *reinterpret_cast<const uint4*>(Bm + (size_t)(k0 + r) * N + n0 + cc);
        }
        __syncthreads();
        #pragma unroll
        for (int ks = 0; ks < 4; ks++) {
            wmma::fragment<wmma::matrix_a, 16, 16, 16, __nv_bfloat16, wmma::row_major> af[2];
            wmma::fragment<wmma::matrix_b, 16, 16, 16, __nv_bfloat16, wmma::row_major> bf[2];
            #pragma unroll
            for (int i = 0; i < 2; i++)
                wmma::load_matrix_sync(af[i], As + (wm * 32 + i * 16) * 72 + ks * 16, 72);
            #pragma unroll
            for (int j = 0; j < 2; j++)
                wmma::load_matrix_sync(bf[j], Bs + (ks * 16) * 72 + wn * 32 + j * 16, 72);
            #pragma unroll
            for (int i = 0; i < 2; i++)
                #pragma unroll
                for (int j = 0; j < 2; j++)
                    wmma::mma_sync(c[i][j], af[i], bf[j], c[i][j]);
        }
        __syncthreads();
    }
    #pragma unroll
    for (int i = 0; i < 2; i++)
        #pragma unroll
        for (int j = 0; j < 2; j++)
            wmma::store_matrix_sync(Cs + (wm * 32 + i * 16) * 68 + wn * 32 + j * 16,
                                    c[i][j], 68, wmma::mem_row_major);
    __syncthreads();
    #pragma unroll 8
    for (int j = 0; j < 32; j++) {
        int u = tid + j * 256;
        int r = u >> 6, cc = u & 63;
        int gm = m0 + r, gn = n0 + cc;
        float val = Cs[r * 68 + cc] + bias[gn];
        if (outb) {
            outb[(size_t)gm * N + gn] = __float2bfloat16(val * alpha);
        } else {
            outf[(size_t)gm * N + gn] = resid[(size_t)gm * N + gn] + gamma[gn] * val;
        }
    }
}

// ---------------- fused bidirectional attention ----------------
#define NSPLIT 8
#define ROWS_PB (KT / NSPLIT)   /* 1024 */
#define NTILES  (ROWS_PB / 64)  /* 16   */
#define ATT_SMEM 54528

__global__ __launch_bounds__(128) void attn_kernel() {
    extern __shared__ char dyn[];
    __nv_bfloat16* ks_ = (__nv_bfloat16*)(dyn);             // k  [64 x 72]
    __nv_bfloat16* vls = (__nv_bfloat16*)(dyn + 9216);      // vl [64 x 72]
    __nv_bfloat16* qs  = (__nv_bfloat16*)(dyn + 18432);     // q tile / e tile (aliased)
    __nv_bfloat16* vvs = (__nv_bfloat16*)(dyn + 27648);     // vv tile
    float*         Sf  = (float*)(dyn + 36864);             // logits/exp/O staging [64 x 68]
    float*         inv = (float*)(dyn + 54272);             // 1/rowsum [64]

    const __nv_bfloat16* qg  = (const __nv_bfloat16*)(g_scratch + OFF_Q);
    const __nv_bfloat16* vvg = (const __nv_bfloat16*)(g_scratch + OFF_VV);
    const __nv_bfloat16* kg  = (const __nv_bfloat16*)(g_scratch + OFF_K);
    const __nv_bfloat16* vlg = (const __nv_bfloat16*)(g_scratch + OFF_VL);
    __nv_bfloat16* ovg = (__nv_bfloat16*)(g_scratch + OFF_OV);
    float* Ug = (float*)(g_scratch + OFF_U);
    float* Zg = (float*)(g_scratch + OFF_Z);

    const int bid = blockIdx.x;
    const int sp  = bid & (NSPLIT - 1);
    const int h   = (bid / NSPLIT) & (KH - 1);
    const int b   = bid / (NSPLIT * KH);
    const int tid = threadIdx.x, wid = tid >> 5;

    #pragma unroll
    for (int j = 0; j < 4; j++) {
        int u = tid + j * 128;
        int r = u >> 3, cc = (u & 7) << 3;
        size_t g = (size_t)(b * KS + r) * KE + h * 64 + cc;
        *reinterpret_cast<uint4*>(ks_ + r * 72 + cc) = *reinterpret_cast<const uint4*>(kg + g);
        *reinterpret_cast<uint4*>(vls + r * 72 + cc) = *reinterpret_cast<const uint4*>(vlg + g);
    }

    wmma::fragment<wmma::accumulator, 16, 16, 16, float> cU[4];
    #pragma unroll
    for (int j = 0; j < 4; j++) wmma::fill_fragment(cU[j], 0.0f);
    float Zreg = 0.0f;
    __syncthreads();

    for (int t = 0; t < NTILES; t++) {
        const int row0 = sp * ROWS_PB + t * 64;
        #pragma unroll
        for (int j = 0; j < 4; j++) {
            int u = tid + j * 128;
            int r = u >> 3, cc = (u & 7) << 3;
            size_t g = (size_t)(b * KT + row0 + r) * KE + h * 64 + cc;
            *reinterpret_cast<uint4*>(qs  + r * 72 + cc) = *reinterpret_cast<const uint4*>(qg  + g);
            *reinterpret_cast<uint4*>(vvs + r * 72 + cc) = *reinterpret_cast<const uint4*>(vvg + g);
        }
        __syncthreads();
        {
            wmma::fragment<wmma::accumulator, 16, 16, 16, float> cS[4];
            #pragma unroll
            for (int j = 0; j < 4; j++) wmma::fill_fragment(cS[j], 0.0f);
            #pragma unroll
            for (int kd = 0; kd < 4; kd++) {
                wmma::fragment<wmma::matrix_a, 16, 16, 16, __nv_bfloat16, wmma::row_major> af;
                wmma::load_matrix_sync(af, qs + wid * 16 * 72 + kd * 16, 72);
                #pragma unroll
                for (int j = 0; j < 4; j++) {
                    wmma::fragment<wmma::matrix_b, 16, 16, 16, __nv_bfloat16, wmma::col_major> bf;
                    wmma::load_matrix_sync(bf, ks_ + kd * 16 + j * 16 * 72, 72);
                    wmma::mma_sync(cS[j], af, bf, cS[j]);
                }
            }
            #pragma unroll
            for (int j = 0; j < 4; j++)
                wmma::store_matrix_sync(Sf + wid * 16 * 68 + j * 16, cS[j], 68, wmma::mem_row_major);
        }
        __syncthreads();
        #pragma unroll 8
        for (int j = 0; j < 32; j++) {
            int u = tid + j * 128;
            int r = u >> 6, s2 = u & 63;
            float e = __expf(Sf[r * 68 + s2]);
            Sf[r * 68 + s2] = e;
            qs[r * 72 + s2] = __float2bfloat16(e);
        }
        __syncthreads();
        if (tid < 64) {
            float rsum = 0.0f;
            #pragma unroll 8
            for (int s2 = 0; s2 < 64; s2++) rsum += Sf[tid * 68 + s2];
            inv[tid] = 1.0f / rsum;
        } else {
            int s2 = tid - 64;
            float cz = 0.0f;
            #pragma unroll 8
            for (int r = 0; r < 64; r++) cz += Sf[r * 68 + s2];
            Zreg += cz;
        }
        __syncthreads();
        {
            wmma::fragment<wmma::accumulator, 16, 16, 16, float> cO[4];
            #pragma unroll
            for (int j = 0; j < 4; j++) wmma::fill_fragment(cO[j], 0.0f);
            #pragma unroll
            for (int ks2 = 0; ks2 < 4; ks2++) {
                wmma::fragment<wmma::matrix_a, 16, 16, 16, __nv_bfloat16, wmma::row_major> af;
                wmma::load_matrix_sync(af, qs + wid * 16 * 72 + ks2 * 16, 72);
                #pragma unroll
                for (int j = 0; j < 4; j++) {
                    wmma::fragment<wmma::matrix_b, 16, 16, 16, __nv_bfloat16, wmma::row_major> bf;
                    wmma::load_matrix_sync(bf, vls + ks2 * 16 * 72 + j * 16, 72);
                    wmma::mma_sync(cO[j], af, bf, cO[j]);
                }
            }
            #pragma unroll
            for (int kt2 = 0; kt2 < 4; kt2++) {
                wmma::fragment<wmma::matrix_a, 16, 16, 16, __nv_bfloat16, wmma::col_major> af;
                wmma::load_matrix_sync(af, qs + wid * 16 + kt2 * 16 * 72, 72);
                #pragma unroll
                for (int j = 0; j < 4; j++) {
                    wmma::fragment<wmma::matrix_b, 16, 16, 16, __nv_bfloat16, wmma::row_major> bf;
                    wmma::load_matrix_sync(bf, vvs + kt2 * 16 * 72 + j * 16, 72);
                    wmma::mma_sync(cU[j], af, bf, cU[j]);
                }
            }
            #pragma unroll
            for (int j = 0; j < 4; j++)
                wmma::store_matrix_sync(Sf + wid * 16 * 68 + j * 16, cO[j], 68, wmma::mem_row_major);
        }
        __syncthreads();
        #pragma unroll
        for (int j = 0; j < 4; j++) {
            int u = tid + j * 128;
            int r = u >> 3, cc = (u & 7) << 3;
            float vi = inv[r];
            uint4 o;
            o.x = pk_bf2(Sf[r * 68 + cc + 0] * vi, Sf[r * 68 + cc + 1] * vi);
            o.y = pk_bf2(Sf[r * 68 + cc + 2] * vi, Sf[r * 68 + cc + 3] * vi);
            o.z = pk_bf2(Sf[r * 68 + cc + 4] * vi, Sf[r * 68 + cc + 5] * vi);
            o.w = pk_bf2(Sf[r * 68 + cc + 6] * vi, Sf[r * 68 + cc + 7] * vi);
            *reinterpret_cast<uint4*>(ovg + (size_t)(b * KT + row0 + r) * KE + h * 64 + cc) = o;
        }
        __syncthreads();
    }
    #pragma unroll
    for (int j = 0; j < 4; j++)
        wmma::store_matrix_sync(Sf + wid * 16 * 68 + j * 16, cU[j], 68, wmma::mem_row_major);
    __syncthreads();
    #pragma unroll 4
    for (int j = 0; j < 32; j++) {
        int u = tid + j * 128;
        int s2 = u >> 6, d = u & 63;
        atomicAdd(&Ug[(((size_t)b * KH + h) * KS + s2) * KHD + d], Sf[s2 * 68 + d]);
    }
    if (tid >= 64) atomicAdd(&Zg[((size_t)b * KH + h) * KS + (tid - 64)], Zreg);
}

// ---------------- merge: out_l = U/Z -> head-merged bf16 [512,1024] ----------------
__global__ void merge_kernel() {
    int i = blockIdx.x * 256 + threadIdx.x;
    const float* Ug = (const float*)(g_scratch + OFF_U);
    const float* Zg = (const float*)(g_scratch + OFF_Z);
    __nv_bfloat16* mg = (__nv_bfloat16*)(g_scratch + OFF_MG);
    int d = i & 63, s = (i >> 6) & 63, h = (i >> 12) & 15, b = i >> 16;
    float val = Ug[i] / Zg[i >> 6];
    mg[(size_t)(b * KS + s) * KE + h * 64 + d] = __float2bfloat16(val);
}

// ---------------- launch ----------------
extern "C" void kernel_launch(void* const* d_in, const int* in_sizes, int n_in,
                              void* d_out, int out_size) {
    (void)in_sizes; (void)n_in; (void)out_size;
    const float* v    = (const float*)d_in[0];
    const float* l    = (const float*)d_in[1];
    const float* vpos = (const float*)d_in[2];
    const float* lnvw = (const float*)d_in[3];
    const float* lnvb = (const float*)d_in[4];
    const float* lnlw = (const float*)d_in[5];
    const float* lnlb = (const float*)d_in[6];
    const float* wq   = (const float*)d_in[7];
    const float* bq   = (const float*)d_in[8];
    const float* wk   = (const float*)d_in[9];
    const float* bk   = (const float*)d_in[10];
    const float* wvv  = (const float*)d_in[11];
    const float* bvv  = (const float*)d_in[12];
    const float* wvl  = (const float*)d_in[13];
    const float* bvl  = (const float*)d_in[14];
    const float* wov  = (const float*)d_in[15];
    const float* bov  = (const float*)d_in[16];
    const float* wol  = (const float*)d_in[17];
    const float* bol  = (const float*)d_in[18];
    const float* gv   = (const float*)d_in[19];
    const float* gl   = (const float*)d_in[20];
    float* outv = (float*)d_out;
    float* outl = outv + (size_t)KMV * KVD;

    unsigned char* base = nullptr;
    cudaGetSymbolAddress((void**)&base, g_scratch);
    cudaFuncSetAttribute(attn_kernel, cudaFuncAttributeMaxDynamicSharedMemorySize, ATT_SMEM);
    cudaFuncSetAttribute(pgemm_kernel, cudaFuncAttributeMaxDynamicSharedMemorySize, PG_SMEM);

    zero_kernel<<<2080, 256>>>();

    // weights -> bf16 (all kept [K,N] row-major)
    cvt_kernel<<<1024, 256>>>(wq,  (__nv_bfloat16*)(base + OFF_WQ),  262144);
    cvt_kernel<<<1024, 256>>>(wvv, (__nv_bfloat16*)(base + OFF_WVV), 262144);
    cvt_kernel<<<1024, 256>>>(wov, (__nv_bfloat16*)(base + OFF_WOV), 262144);
    cvt_kernel<<<3072, 256>>>(wk,  (__nv_bfloat16*)(base + OFF_WK),  786432);
    cvt_kernel<<<3072, 256>>>(wvl, (__nv_bfloat16*)(base + OFF_WVL), 786432);
    cvt_kernel<<<3072, 256>>>(wol, (__nv_bfloat16*)(base + OFF_WOL), 786432);

    lnl_kernel<<<KML, 256>>>(l, lnlw, lnlb);
    lnv_kernel<<<KMV / 8, 256>>>(v, vpos, lnvw, lnvb);

    // big projections via pipelined GEMM
    pgemm_kernel<<<dim3(KE / 128, KMV / 128), 256, PG_SMEM>>>(
        (__nv_bfloat16*)(base + OFF_QIN), (__nv_bfloat16*)(base + OFF_WQ),
        bq, QK_SCALE, nullptr, nullptr,
        (__nv_bfloat16*)(base + OFF_Q), nullptr, KMV, KE, KVD);
    pgemm_kernel<<<dim3(KE / 128, KMV / 128), 256, PG_SMEM>>>(
        (__nv_bfloat16*)(base + OFF_VN), (__nv_bfloat16*)(base + OFF_WVV),
        bvv, 1.0f, nullptr, nullptr,
        (__nv_bfloat16*)(base + OFF_VV), nullptr, KMV, KE, KVD);

    // small l-side projections via basic wmma
    gemm_kernel<<<dim3(KE / GBN, KML / GBM), 256>>>(
        (__nv_bfloat16*)(base + OFF_LN), (__nv_bfloat16*)(base + OFF_WK),
        bk, 1.0f, nullptr, nullptr,
        (__nv_bfloat16*)(base + OFF_K), nullptr, KML, KE, KLD);
    gemm_kernel<<<dim3(KE / GBN, KML / GBM), 256>>>(
        (__nv_bfloat16*)(base + OFF_LN), (__nv_bfloat16*)(base + OFF_WVL),
        bvl, 1.0f, nullptr, nullptr,
        (__nv_bfloat16*)(base + OFF_VL), nullptr, KML, KE, KLD);

    // fused bidirectional attention
    attn_kernel<<<KB * KH * NSPLIT, 128, ATT_SMEM>>>();

    // output projections
    merge_kernel<<<2048, 256>>>();
    pgemm_kernel<<<dim3(KVD / 128, KMV / 128), 256, PG_SMEM>>>(
        (__nv_bfloat16*)(base + OFF_OV), (__nv_bfloat16*)(base + OFF_WOV),
        bov, 1.0f, v, gv, nullptr, outv, KMV, KVD, KE);
    gemm_kernel<<<dim3(KLD / GBN, KML / GBM), 256>>>(
        (__nv_bfloat16*)(base + OFF_MG), (__nv_bfloat16*)(base + OFF_WOL),
        bol, 1.0f, l, gl, nullptr, outl, KML, KLD, KE);
}

// round 7
// speedup vs baseline: 1.0893x; 1.0305x over previous
#include <cuda_runtime.h>
#include <cuda_bf16.h>
#include <mma.h>
#include <cstdint>
#include <cstddef>

using namespace nvcuda;

// ---------------- problem constants ----------------
#define KB     8
#define KT     8192
#define KS     64
#define KVD    256
#define KLD    768
#define KE     1024
#define KH     16
#define KHD    64
#define KMV    (KB*KT)     /* 65536 */
#define KML    (KB*KS)     /* 512   */
#define QK_SCALE 0.125f

// ---------------- scratch layout (single __device__ arena) ----------------
#define OFF_VN   ((size_t)0)                      /* [65536,256] bf16 */
#define OFF_QIN  ((size_t)33554432)               /* [65536,256] bf16 */
#define OFF_Q    ((size_t)67108864)               /* [65536,1024] bf16 */
#define OFF_VV   ((size_t)201326592)              /* [65536,1024] bf16 */
#define OFF_OV   ((size_t)335544320)              /* [65536,1024] bf16 */
#define OFF_LN   ((size_t)469762048)              /* [512,768] bf16 */
#define OFF_K    ((size_t)470548480)              /* [512,1024] bf16 */
#define OFF_VL   ((size_t)471597056)              /* [512,1024] bf16 */
#define OFF_MG   ((size_t)472645632)              /* [512,1024] bf16 */
#define OFF_U    ((size_t)473694208)              /* [8,16,64,64] f32 */
#define OFF_Z    ((size_t)475791360)              /* [8,16,64] f32 */
#define OFF_WQ   ((size_t)475824128)              /* [256,1024] bf16 */
#define OFF_WVV  ((size_t)476348416)              /* [256,1024] bf16 */
#define OFF_WOV  ((size_t)476872704)              /* [1024,256] bf16 */
#define OFF_WK   ((size_t)477396992)              /* [768,1024] bf16 */
#define OFF_WVL  ((size_t)478969856)              /* [768,1024] bf16 */
#define OFF_WOL  ((size_t)480542720)              /* [1024,768] bf16 */
#define SCRATCH_BYTES ((size_t)482115584)

__device__ __align__(256) unsigned char g_scratch[SCRATCH_BYTES];

// ---------------- helpers ----------------
__device__ __forceinline__ uint32_t pk_bf2(float a, float b) {
    __nv_bfloat162 t = __floats2bfloat162_rn(a, b);
    return *reinterpret_cast<uint32_t*>(&t);
}
__device__ __forceinline__ uint32_t smem_u32(const void* p) {
    uint32_t a;
    asm("{ .reg .u64 t; cvta.to.shared.u64 t, %1; cvt.u32.u64 %0, t; }" : "=r"(a) : "l"(p));
    return a;
}
__device__ __forceinline__ void cp16(uint32_t dst, const void* src) {
    asm volatile("cp.async.cg.shared.global [%0], [%1], 16;\n" :: "r"(dst), "l"(src));
}
__device__ __forceinline__ void cp_commit() {
    asm volatile("cp.async.commit_group;\n" ::);
}
// Schraudolph fast exp: FFMA + F2I. Max rel err ~3%; logits are in [-4,4].
// Bias centered: 1065353216 - 355556.
__device__ __forceinline__ float fexp(float x) {
    float y = fmaf(x, 12102203.1616f, 1064997660.0f);
    return __int_as_float((int)y);
}

// ---------------- prep: zero U/Z + all weight converts (ONE launch) ----------------
__global__ void prep_kernel(const float* __restrict__ wq,  const float* __restrict__ wvv,
                            const float* __restrict__ wov, const float* __restrict__ wk,
                            const float* __restrict__ wvl, const float* __restrict__ wol) {
    int i = blockIdx.x * 256 + threadIdx.x;
    if (i < 532480) ((float*)(g_scratch + OFF_U))[i] = 0.0f;
    if (i < 262144) {
        ((__nv_bfloat16*)(g_scratch + OFF_WQ))[i] = __float2bfloat16(wq[i]);
    } else if (i < 524288) {
        int j = i - 262144;
        ((__nv_bfloat16*)(g_scratch + OFF_WVV))[j] = __float2bfloat16(wvv[j]);
    } else if (i < 786432) {
        int j = i - 524288;
        ((__nv_bfloat16*)(g_scratch + OFF_WOV))[j] = __float2bfloat16(wov[j]);
    } else if (i < 1572864) {
        int j = i - 786432;
        ((__nv_bfloat16*)(g_scratch + OFF_WK))[j] = __float2bfloat16(wk[j]);
    } else if (i < 2359296) {
        int j = i - 1572864;
        ((__nv_bfloat16*)(g_scratch + OFF_WVL))[j] = __float2bfloat16(wvl[j]);
    } else if (i < 3145728) {
        int j = i - 2359296;
        ((__nv_bfloat16*)(g_scratch + OFF_WOL))[j] = __float2bfloat16(wol[j]);
    }
}

// ---------------- LayerNorm(v) + v_pos ----------------
__global__ __launch_bounds__(256) void lnv_kernel(const float* __restrict__ v,
                                                  const float* __restrict__ vp,
                                                  const float* __restrict__ w,
                                                  const float* __restrict__ b) {
    int row  = blockIdx.x * 8 + (threadIdx.x >> 5);
    int lane = threadIdx.x & 31;
    const float4* vr = reinterpret_cast<const float4*>(v + (size_t)row * KVD) + lane * 2;
    float4 x0 = vr[0], x1 = vr[1];
    float s = x0.x + x0.y + x0.z + x0.w + x1.x + x1.y + x1.z + x1.w;
    float q = x0.x*x0.x + x0.y*x0.y + x0.z*x0.z + x0.w*x0.w
            + x1.x*x1.x + x1.y*x1.y + x1.z*x1.z + x1.w*x1.w;
    #pragma unroll
    for (int o = 16; o > 0; o >>= 1) {
        s += __shfl_xor_sync(0xffffffffu, s, o);
        q += __shfl_xor_sync(0xffffffffu, q, o);
    }
    float mu   = s * (1.0f / KVD);
    float var  = q * (1.0f / KVD) - mu * mu;
    float rstd = rsqrtf(var + 1e-5f);

    const float4* vpr = reinterpret_cast<const float4*>(vp + (size_t)row * KVD) + lane * 2;
    float4 p0 = vpr[0], p1 = vpr[1];
    const float4* w4 = reinterpret_cast<const float4*>(w) + lane * 2;
    const float4* b4 = reinterpret_cast<const float4*>(b) + lane * 2;
    float4 wa = w4[0], wb = w4[1], ba = b4[0], bb = b4[1];

    float n0 = (x0.x - mu) * rstd * wa.x + ba.x;
    float n1 = (x0.y - mu) * rstd * wa.y + ba.y;
    float n2 = (x0.z - mu) * rstd * wa.z + ba.z;
    float n3 = (x0.w - mu) * rstd * wa.w + ba.w;
    float n4 = (x1.x - mu) * rstd * wb.x + bb.x;
    float n5 = (x1.y - mu) * rstd * wb.y + bb.y;
    float n6 = (x1.z - mu) * rstd * wb.z + bb.z;
    float n7 = (x1.w - mu) * rstd * wb.w + bb.w;

    uint4 on; on.x = pk_bf2(n0,n1); on.y = pk_bf2(n2,n3); on.z = pk_bf2(n4,n5); on.w = pk_bf2(n6,n7);
    uint4 oq; oq.x = pk_bf2(n0+p0.x, n1+p0.y); oq.y = pk_bf2(n2+p0.z, n3+p0.w);
    oq.z = pk_bf2(n4+p1.x, n5+p1.y); oq.w = pk_bf2(n6+p1.z, n7+p1.w);

    __nv_bfloat16* vn  = (__nv_bfloat16*)(g_scratch + OFF_VN);
    __nv_bfloat16* qin = (__nv_bfloat16*)(g_scratch + OFF_QIN);
    *reinterpret_cast<uint4*>(vn  + (size_t)row * KVD + lane * 8) = on;
    *reinterpret_cast<uint4*>(qin + (size_t)row * KVD + lane * 8) = oq;
}

// ---------------- LayerNorm(l) ----------------
__global__ __launch_bounds__(256) void lnl_kernel(const float* __restrict__ l,
                                                  const float* __restrict__ w,
                                                  const float* __restrict__ b) {
    int row = blockIdx.x, tid = threadIdx.x;
    const float* lr = l + (size_t)row * KLD;
    float x0 = lr[tid], x1 = lr[tid + 256], x2 = lr[tid + 512];
    float s = x0 + x1 + x2;
    float q = x0*x0 + x1*x1 + x2*x2;
    #pragma unroll
    for (int o = 16; o > 0; o >>= 1) {
        s += __shfl_xor_sync(0xffffffffu, s, o);
        q += __shfl_xor_sync(0xffffffffu, q, o);
    }
    __shared__ float rs[8], rq[8];
    if ((tid & 31) == 0) { rs[tid >> 5] = s; rq[tid >> 5] = q; }
    __syncthreads();
    float S = 0.f, Q = 0.f;
    #pragma unroll
    for (int i = 0; i < 8; i++) { S += rs[i]; Q += rq[i]; }
    float mu = S * (1.0f / KLD);
    float var = Q * (1.0f / KLD) - mu * mu;
    float rstd = rsqrtf(var + 1e-5f);
    __nv_bfloat16* out = (__nv_bfloat16*)(g_scratch + OFF_LN) + (size_t)row * KLD;
    out[tid]       = __float2bfloat16((x0 - mu) * rstd * w[tid]       + b[tid]);
    out[tid + 256] = __float2bfloat16((x1 - mu) * rstd * w[tid + 256] + b[tid + 256]);
    out[tid + 512] = __float2bfloat16((x2 - mu) * rstd * w[tid + 512] + b[tid + 512]);
}

// ============================================================================
// Pipelined GEMM (unchanged from R6)
// ============================================================================
#define PG_STAGE 35840
#define PG_SMEM  (2 * PG_STAGE)

__global__ __launch_bounds__(256) void pgemm_kernel(
    const __nv_bfloat16* __restrict__ A, const __nv_bfloat16* __restrict__ Bm,
    const float* __restrict__ bias, float alpha,
    const float* __restrict__ resid, const float* __restrict__ gamma,
    __nv_bfloat16* __restrict__ outb, float* __restrict__ outf,
    int M, int N, int K)
{
    extern __shared__ __align__(16) char ps[];
    const uint32_t sb = smem_u32(ps);
    const int tid = threadIdx.x, wid = tid >> 5;
    const int m0 = blockIdx.y * 128, n0 = blockIdx.x * 128;
    const int wm = wid >> 2, wn = wid & 3;

    wmma::fragment<wmma::accumulator, 16, 16, 16, float> acc[4][2];
    #pragma unroll
    for (int i = 0; i < 4; i++)
        #pragma unroll
        for (int j = 0; j < 2; j++) wmma::fill_fragment(acc[i][j], 0.0f);

    const int NK = K >> 6;
    {
        const __nv_bfloat16* Ag = A + (size_t)m0 * K;
        const __nv_bfloat16* Bg = Bm + n0;
        uint32_t ab = sb, bb = sb + 18432;
        #pragma unroll
        for (int j = 0; j < 4; j++) {
            int u = tid + j * 256; int r = u >> 3, c8 = (u & 7) << 3;
            cp16(ab + (uint32_t)(r * 72 + c8) * 2, Ag + (size_t)r * K + c8);
        }
        #pragma unroll
        for (int j = 0; j < 4; j++) {
            int u = tid + j * 256; int r = u >> 4, c8 = (u & 15) << 3;
            cp16(bb + (uint32_t)(r * 136 + c8) * 2, Bg + (size_t)r * N + c8);
        }
        cp_commit();
    }

    for (int kc = 0; kc < NK; kc++) {
        if (kc + 1 < NK) {
            const int st = (kc + 1) & 1;
            const __nv_bfloat16* Ag = A + (size_t)m0 * K + (kc + 1) * 64;
            const __nv_bfloat16* Bg = Bm + (size_t)((kc + 1) * 64) * N + n0;
            uint32_t ab = sb + st * PG_STAGE, bb = ab + 18432;
            #pragma unroll
            for (int j = 0; j < 4; j++) {
                int u = tid + j * 256; int r = u >> 3, c8 = (u & 7) << 3;
                cp16(ab + (uint32_t)(r * 72 + c8) * 2, Ag + (size_t)r * K + c8);
            }
            #pragma unroll
            for (int j = 0; j < 4; j++) {
                int u = tid + j * 256; int r = u >> 4, c8 = (u & 15) << 3;
                cp16(bb + (uint32_t)(r * 136 + c8) * 2, Bg + (size_t)r * N + c8);
            }
            cp_commit();
            asm volatile("cp.async.wait_group 1;\n" ::);
        } else {
            asm volatile("cp.async.wait_group 0;\n" ::);
        }
        __syncthreads();

        const __nv_bfloat16* As = (const __nv_bfloat16*)(ps + (kc & 1) * PG_STAGE);
        const __nv_bfloat16* Bs = (const __nv_bfloat16*)(ps + (kc & 1) * PG_STAGE + 18432);
        #pragma unroll
        for (int ks = 0; ks < 4; ks++) {
            wmma::fragment<wmma::matrix_a, 16, 16, 16, __nv_bfloat16, wmma::row_major> af[4];
            wmma::fragment<wmma::matrix_b, 16, 16, 16, __nv_bfloat16, wmma::row_major> bf[2];
            #pragma unroll
            for (int i = 0; i < 4; i++)
                wmma::load_matrix_sync(af[i], As + (wm * 64 + i * 16) * 72 + ks * 16, 72);
            #pragma unroll
            for (int j = 0; j < 2; j++)
                wmma::load_matrix_sync(bf[j], Bs + (ks * 16) * 136 + wn * 32 + j * 16, 136);
            #pragma unroll
            for (int i = 0; i < 4; i++)
                #pragma unroll
                for (int j = 0; j < 2; j++)
                    wmma::mma_sync(acc[i][j], af[i], bf[j], acc[i][j]);
        }
        __syncthreads();
    }

    float* Cs = (float*)ps;
    #pragma unroll
    for (int i = 0; i < 4; i++)
        #pragma unroll
        for (int j = 0; j < 2; j++)
            wmma::store_matrix_sync(Cs + (wm * 64 + i * 16) * 132 + wn * 32 + j * 16,
                                    acc[i][j], 132, wmma::mem_row_major);
    __syncthreads();

    if (outb) {
        #pragma unroll
        for (int j = 0; j < 8; j++) {
            int u = tid + j * 256;
            int r = u >> 4, c8 = (u & 15) << 3;
            int gm = m0 + r, gc = n0 + c8;
            uint32_t pk[4];
            #pragma unroll
            for (int i = 0; i < 4; i++) {
                float a0 = (Cs[r * 132 + c8 + 2*i]     + bias[gc + 2*i])     * alpha;
                float a1 = (Cs[r * 132 + c8 + 2*i + 1] + bias[gc + 2*i + 1]) * alpha;
                pk[i] = pk_bf2(a0, a1);
            }
            *reinterpret_cast<uint4*>(outb + (size_t)gm * N + gc) =
                make_uint4(pk[0], pk[1], pk[2], pk[3]);
        }
    } else {
        #pragma unroll
        for (int j = 0; j < 8; j++) {
            int u = tid + j * 256;
            int r = u >> 4, c8 = (u & 15) << 3;
            int gm = m0 + r, gc = n0 + c8;
            const float4* rsd = reinterpret_cast<const float4*>(resid + (size_t)gm * N + gc);
            float4* dst = reinterpret_cast<float4*>(outf + (size_t)gm * N + gc);
            #pragma unroll
            for (int i = 0; i < 2; i++) {
                float4 rv = rsd[i];
                float4 o;
                o.x = rv.x + gamma[gc + 4*i + 0] * (Cs[r * 132 + c8 + 4*i + 0] + bias[gc + 4*i + 0]);
                o.y = rv.y + gamma[gc + 4*i + 1] * (Cs[r * 132 + c8 + 4*i + 1] + bias[gc + 4*i + 1]);
                o.z = rv.z + gamma[gc + 4*i + 2] * (Cs[r * 132 + c8 + 4*i + 2] + bias[gc + 4*i + 2]);
                o.w = rv.w + gamma[gc + 4*i + 3] * (Cs[r * 132 + c8 + 4*i + 3] + bias[gc + 4*i + 3]);
                dst[i] = o;
            }
        }
    }
}

// ---------------- wmma GEMM (small l-side GEMMs only) ----------------
#define GBM 128
#define GBN 64
#define GBK 64
__global__ __launch_bounds__(256) void gemm_kernel(
    const __nv_bfloat16* __restrict__ A, const __nv_bfloat16* __restrict__ Bm,
    const float* __restrict__ bias, float alpha,
    const float* __restrict__ resid, const float* __restrict__ gamma,
    __nv_bfloat16* __restrict__ outb, float* __restrict__ outf,
    int M, int N, int K)
{
    __shared__ __align__(16) unsigned char smem_raw[34816];
    __nv_bfloat16* As = (__nv_bfloat16*)smem_raw;
    __nv_bfloat16* Bs = (__nv_bfloat16*)(smem_raw + 18432);
    float* Cs = (float*)smem_raw;

    const int tid = threadIdx.x;
    const int wid = tid >> 5;
    const int m0 = blockIdx.y * GBM;
    const int n0 = blockIdx.x * GBN;
    const int wm = wid & 3, wn = wid >> 2;

    wmma::fragment<wmma::accumulator, 16, 16, 16, float> c[2][2];
    #pragma unroll
    for (int i = 0; i < 2; i++)
        #pragma unroll
        for (int j = 0; j < 2; j++) wmma::fill_fragment(c[i][j], 0.0f);

    for (int k0 = 0; k0 < K; k0 += GBK) {
        #pragma unroll
        for (int j = 0; j < 4; j++) {
            int u = tid + j * 256;
            int r = u >> 3, cc = (u & 7) << 3;
            *reinterpret_cast<uint4*>(As + r * 72 + cc) =
                *reinterpret_cast<const uint4*>(A + (size_t)(m0 + r) * K + k0 + cc);
        }
        #pragma unroll
        for (int j = 0; j < 2; j++) {
            int u = tid + j * 256;
            int r = u >> 3, cc = (u & 7) << 3;
            *reinterpret_cast<uint4*>(Bs + r * 72 + cc) =
                *reinterpret_cast<const uint4*>(Bm + (size_t)(k0 + r) * N + n0 + cc);
        }
        __syncthreads();
        #pragma unroll
        for (int ks = 0; ks < 4; ks++) {
            wmma::fragment<wmma::matrix_a, 16, 16, 16, __nv_bfloat16, wmma::row_major> af[2];
            wmma::fragment<wmma::matrix_b, 16, 16, 16, __nv_bfloat16, wmma::row_major> bf[2];
            #pragma unroll
            for (int i = 0; i < 2; i++)
                wmma::load_matrix_sync(af[i], As + (wm * 32 + i * 16) * 72 + ks * 16, 72);
            #pragma unroll
            for (int j = 0; j < 2; j++)
                wmma::load_matrix_sync(bf[j], Bs + (ks * 16) * 72 + wn * 32 + j * 16, 72);
            #pragma unroll
            for (int i = 0; i < 2; i++)
                #pragma unroll
                for (int j = 0; j < 2; j++)
                    wmma::mma_sync(c[i][j], af[i], bf[j], c[i][j]);
        }
        __syncthreads();
    }
    #pragma unroll
    for (int i = 0; i < 2; i++)
        #pragma unroll
        for (int j = 0; j < 2; j++)
            wmma::store_matrix_sync(Cs + (wm * 32 + i * 16) * 68 + wn * 32 + j * 16,
                                    c[i][j], 68, wmma::mem_row_major);
    __syncthreads();
    #pragma unroll 8
    for (int j = 0; j < 32; j++) {
        int u = tid + j * 256;
        int r = u >> 6, cc = u & 63;
        int gm = m0 + r, gn = n0 + cc;
        float val = Cs[r * 68 + cc] + bias[gn];
        if (outb) {
            outb[(size_t)gm * N + gn] = __float2bfloat16(val * alpha);
        } else {
            outf[(size_t)gm * N + gn] = resid[(size_t)gm * N + gn] + gamma[gn] * val;
        }
    }
}

// ============================================================================
// Fused bidirectional attention v2.
// 256 threads (8 warps), 128-row T-tiles, fast-exp on fragments,
// ones-columns in vl/vv give rowsum (p_v denom) and colsum (Z) via MMA.
// ============================================================================
#define ANS    8                 /* T splits per (b,h) */
#define AROWS  128
#define ATILES (KT / ANS / AROWS) /* 8 */
// smem byte offsets
#define AT_KS   0                 /* k   64 x 72 bf16 =  9216 */
#define AT_VLS  9216              /* vl  64 x 88 bf16 = 11264 (cols 64..79: ones block) */
#define AT_QS   20480             /* q/e 128 x 72 bf16 = 18432 */
#define AT_VVS  38912             /* vv  128 x 88 bf16 = 22528 (cols 64..79: ones block) */
#define AT_SF   61440             /* S/O/U staging 128 x 84 f32 = 43008 */
#define AT_SMEM 104448

__global__ __launch_bounds__(256, 2) void attn2_kernel() {
    extern __shared__ char dyn[];
    __nv_bfloat16* ks_ = (__nv_bfloat16*)(dyn + AT_KS);
    __nv_bfloat16* vls = (__nv_bfloat16*)(dyn + AT_VLS);
    __nv_bfloat16* qs  = (__nv_bfloat16*)(dyn + AT_QS);
    __nv_bfloat16* vvs = (__nv_bfloat16*)(dyn + AT_VVS);
    float*         Sf  = (float*)(dyn + AT_SF);

    const __nv_bfloat16* qg  = (const __nv_bfloat16*)(g_scratch + OFF_Q);
    const __nv_bfloat16* vvg = (const __nv_bfloat16*)(g_scratch + OFF_VV);
    const __nv_bfloat16* kg  = (const __nv_bfloat16*)(g_scratch + OFF_K);
    const __nv_bfloat16* vlg = (const __nv_bfloat16*)(g_scratch + OFF_VL);
    __nv_bfloat16* ovg = (__nv_bfloat16*)(g_scratch + OFF_OV);
    float* Ug = (float*)(g_scratch + OFF_U);
    float* Zg = (float*)(g_scratch + OFF_Z);

    const int bid = blockIdx.x;
    const int sp  = bid & (ANS - 1);
    const int h   = (bid >> 3) & (KH - 1);
    const int b   = bid >> 7;
    const int tid = threadIdx.x, wid = tid >> 5, lane = tid & 31;

    // load k, vl [64 x 64]
    #pragma unroll
    for (int j = 0; j < 2; j++) {
        int u = tid + j * 256;
        int r = u >> 3, c8 = (u & 7) << 3;
        size_t g = (size_t)(b * KS + r) * KE + h * 64 + c8;
        *reinterpret_cast<uint4*>(ks_ + r * 72 + c8) = *reinterpret_cast<const uint4*>(kg + g);
        *reinterpret_cast<uint4*>(vls + r * 88 + c8) = *reinterpret_cast<const uint4*>(vlg + g);
    }
    // ones blocks: col 64 = 1, cols 65..79 = 0
    const __nv_bfloat16 one_bf = __float2bfloat16(1.0f);
    const __nv_bfloat16 zero_bf = __float2bfloat16(0.0f);
    for (int u = tid; u < 64 * 16; u += 256) {
        int r = u >> 4, c = u & 15;
        vls[r * 88 + 64 + c] = (c == 0) ? one_bf : zero_bf;
    }
    for (int u = tid; u < 128 * 16; u += 256) {
        int r = u >> 4, c = u & 15;
        vvs[r * 88 + 64 + c] = (c == 0) ? one_bf : zero_bf;
    }

    wmma::fragment<wmma::accumulator, 16, 16, 16, float> cU[5];
    #pragma unroll
    for (int j = 0; j < 5; j++) wmma::fill_fragment(cU[j], 0.0f);
    __syncthreads();

    const int wu_s  = (wid & 3) * 16;   // U: s-row block
    const int wu_k0 = (wid >> 2) * 4;   // U: t-block offset (two warp groups split k)

    for (int t = 0; t < ATILES; t++) {
        const int row0 = sp * (KT / ANS) + t * AROWS;
        // load q, vv [128 x 64]
        #pragma unroll
        for (int j = 0; j < 4; j++) {
            int u = tid + j * 256;
            int r = u >> 3, c8 = (u & 7) << 3;
            size_t g = (size_t)(b * KT + row0 + r) * KE + h * 64 + c8;
            *reinterpret_cast<uint4*>(qs  + r * 72 + c8) = *reinterpret_cast<const uint4*>(qg  + g);
            *reinterpret_cast<uint4*>(vvs + r * 88 + c8) = *reinterpret_cast<const uint4*>(vvg + g);
        }
        __syncthreads();

        // ---- S = q @ k^T (warp owns 16 rows), exp on fragments, store fp32 e
        {
            wmma::fragment<wmma::matrix_a, 16, 16, 16, __nv_bfloat16, wmma::row_major> af[4];
            #pragma unroll
            for (int kd = 0; kd < 4; kd++)
                wmma::load_matrix_sync(af[kd], qs + (wid * 16) * 72 + kd * 16, 72);
            #pragma unroll
            for (int j = 0; j < 4; j++) {
                wmma::fragment<wmma::accumulator, 16, 16, 16, float> cS;
                wmma::fill_fragment(cS, 0.0f);
                #pragma unroll
                for (int kd = 0; kd < 4; kd++) {
                    wmma::fragment<wmma::matrix_b, 16, 16, 16, __nv_bfloat16, wmma::col_major> bf;
                    wmma::load_matrix_sync(bf, ks_ + kd * 16 + j * 16 * 72, 72);
                    wmma::mma_sync(cS, af[kd], bf, cS);
                }
                #pragma unroll
                for (int e = 0; e < cS.num_elements; e++) cS.x[e] = fexp(cS.x[e]);
                wmma::store_matrix_sync(Sf + (wid * 16) * 84 + j * 16, cS, 84, wmma::mem_row_major);
            }
        }
        __syncwarp();
        // ---- convert own rows fp32 -> bf16 into qs (e tile)
        {
            int r = wid * 16 + (lane >> 1);
            int c0 = (lane & 1) * 32;
            const float4* src = reinterpret_cast<const float4*>(Sf + r * 84 + c0);
            uint4* dst = reinterpret_cast<uint4*>(qs + r * 72 + c0);
            #pragma unroll
            for (int i = 0; i < 4; i++) {
                float4 a = src[2*i], bb2 = src[2*i + 1];
                dst[i] = make_uint4(pk_bf2(a.x, a.y), pk_bf2(a.z, a.w),
                                    pk_bf2(bb2.x, bb2.y), pk_bf2(bb2.z, bb2.w));
            }
        }
        __syncthreads();

        // ---- O = e @ [vl | 1] (warp owns 16 rows x 80 cols); col 64 = rowsum
        {
            wmma::fragment<wmma::matrix_a, 16, 16, 16, __nv_bfloat16, wmma::row_major> afO[4];
            #pragma unroll
            for (int k2 = 0; k2 < 4; k2++)
                wmma::load_matrix_sync(afO[k2], qs + (wid * 16) * 72 + k2 * 16, 72);
            #pragma unroll
            for (int j = 0; j < 5; j++) {
                wmma::fragment<wmma::accumulator, 16, 16, 16, float> cO;
                wmma::fill_fragment(cO, 0.0f);
                #pragma unroll
                for (int k2 = 0; k2 < 4; k2++) {
                    wmma::fragment<wmma::matrix_b, 16, 16, 16, __nv_bfloat16, wmma::row_major> bf;
                    wmma::load_matrix_sync(bf, vls + (k2 * 16) * 88 + j * 16, 88);
                    wmma::mma_sync(cO, afO[k2], bf, cO);
                }
                wmma::store_matrix_sync(Sf + (wid * 16) * 84 + j * 16, cO, 84, wmma::mem_row_major);
            }
        }
        // ---- U += e^T @ [vv | 1] (persistent; warp groups split the 128-t dim)
        {
            #pragma unroll
            for (int i = 0; i < 4; i++) {
                wmma::fragment<wmma::matrix_a, 16, 16, 16, __nv_bfloat16, wmma::col_major> afU;
                wmma::load_matrix_sync(afU, qs + ((wu_k0 + i) * 16) * 72 + wu_s, 72);
                #pragma unroll
                for (int j = 0; j < 5; j++) {
                    wmma::fragment<wmma::matrix_b, 16, 16, 16, __nv_bfloat16, wmma::row_major> bf;
                    wmma::load_matrix_sync(bf, vvs + ((wu_k0 + i) * 16) * 88 + j * 16, 88);
                    wmma::mma_sync(cU[j], afU, bf, cU[j]);
                }
            }
        }
        __syncthreads();

        // ---- normalize + write out_v (bf16, head-interleaved)
        {
            int r = tid >> 1;
            int c0 = (tid & 1) * 32;
            float inv = 1.0f / Sf[r * 84 + 64];
            const float4* src = reinterpret_cast<const float4*>(Sf + r * 84 + c0);
            uint4* dst = reinterpret_cast<uint4*>(ovg + (size_t)(b * KT + row0 + r) * KE + h * 64 + c0);
            #pragma unroll
            for (int i = 0; i < 4; i++) {
                float4 a = src[2*i], bb2 = src[2*i + 1];
                dst[i] = make_uint4(pk_bf2(a.x * inv, a.y * inv), pk_bf2(a.z * inv, a.w * inv),
                                    pk_bf2(bb2.x * inv, bb2.y * inv), pk_bf2(bb2.z * inv, bb2.w * inv));
            }
        }
        // no trailing sync needed: next tile's loads touch qs/vvs (done being read),
        // and Sf is only rewritten after the next post-load __syncthreads.
    }

    // ---- flush U (two partial halves) and Z
    __syncthreads();
    #pragma unroll
    for (int j = 0; j < 5; j++)
        wmma::store_matrix_sync(Sf + ((wid >> 2) * 64 + (wid & 3) * 16) * 84 + j * 16,
                                cU[j], 84, wmma::mem_row_major);
    __syncthreads();
    #pragma unroll
    for (int j = 0; j < 16; j++) {
        int u = tid + j * 256;
        int s2 = u >> 6, d = u & 63;
        float val = Sf[s2 * 84 + d] + Sf[(64 + s2) * 84 + d];
        atomicAdd(&Ug[(((size_t)b * KH + h) * KS + s2) * KHD + d], val);
    }
    if (tid < 64)
        atomicAdd(&Zg[((size_t)b * KH + h) * KS + tid],
                  Sf[tid * 84 + 64] + Sf[(64 + tid) * 84 + 64]);
}

// ---------------- merge: out_l = U/Z -> head-merged bf16 [512,1024] ----------------
__global__ void merge_kernel() {
    int i = blockIdx.x * 256 + threadIdx.x;
    const float* Ug = (const float*)(g_scratch + OFF_U);
    const float* Zg = (const float*)(g_scratch + OFF_Z);
    __nv_bfloat16* mg = (__nv_bfloat16*)(g_scratch + OFF_MG);
    int d = i & 63, s = (i >> 6) & 63, h = (i >> 12) & 15, b = i >> 16;
    float val = Ug[i] / Zg[i >> 6];
    mg[(size_t)(b * KS + s) * KE + h * 64 + d] = __float2bfloat16(val);
}

// ---------------- launch ----------------
// Launch order matters for ncu (-s 5 -c 1 captures launch index 5 = pgemm q).
extern "C" void kernel_launch(void* const* d_in, const int* in_sizes, int n_in,
                              void* d_out, int out_size) {
    (void)in_sizes; (void)n_in; (void)out_size;
    const float* v    = (const float*)d_in[0];
    const float* l    = (const float*)d_in[1];
    const float* vpos = (const float*)d_in[2];
    const float* lnvw = (const float*)d_in[3];
    const float* lnvb = (const float*)d_in[4];
    const float* lnlw = (const float*)d_in[5];
    const float* lnlb = (const float*)d_in[6];
    const float* wq   = (const float*)d_in[7];
    const float* bq   = (const float*)d_in[8];
    const float* wk   = (const float*)d_in[9];
    const float* bk   = (const float*)d_in[10];
    const float* wvv  = (const float*)d_in[11];
    const float* bvv  = (const float*)d_in[12];
    const float* wvl  = (const float*)d_in[13];
    const float* bvl  = (const float*)d_in[14];
    const float* wov  = (const float*)d_in[15];
    const float* bov  = (const float*)d_in[16];
    const float* wol  = (const float*)d_in[17];
    const float* bol  = (const float*)d_in[18];
    const float* gv   = (const float*)d_in[19];
    const float* gl   = (const float*)d_in[20];
    float* outv = (float*)d_out;
    float* outl = outv + (size_t)KMV * KVD;

    unsigned char* base = nullptr;
    cudaGetSymbolAddress((void**)&base, g_scratch);
    cudaFuncSetAttribute(attn2_kernel, cudaFuncAttributeMaxDynamicSharedMemorySize, AT_SMEM);
    cudaFuncSetAttribute(pgemm_kernel, cudaFuncAttributeMaxDynamicSharedMemorySize, PG_SMEM);

    // 0: zero accumulators + all weight converts
    prep_kernel<<<14352, 256>>>(wq, wvv, wov, wk, wvl, wol);
    // 1-2: layernorms
    lnl_kernel<<<KML, 256>>>(l, lnlw, lnlb);
    lnv_kernel<<<KMV / 8, 256>>>(v, vpos, lnvw, lnvb);
    // 3-4: small l-side projections
    gemm_kernel<<<dim3(KE / GBN, KML / GBM), 256>>>(
        (__nv_bfloat16*)(base + OFF_LN), (__nv_bfloat16*)(base + OFF_WK),
        bk, 1.0f, nullptr, nullptr,
        (__nv_bfloat16*)(base + OFF_K), nullptr, KML, KE, KLD);
    gemm_kernel<<<dim3(KE / GBN, KML / GBM), 256>>>(
        (__nv_bfloat16*)(base + OFF_LN), (__nv_bfloat16*)(base + OFF_WVL),
        bvl, 1.0f, nullptr, nullptr,
        (__nv_bfloat16*)(base + OFF_VL), nullptr, KML, KE, KLD);
    // 5-6: big projections (launch 5 is ncu's capture target)
    pgemm_kernel<<<dim3(KE / 128, KMV / 128), 256, PG_SMEM>>>(
        (__nv_bfloat16*)(base + OFF_QIN), (__nv_bfloat16*)(base + OFF_WQ),
        bq, QK_SCALE, nullptr, nullptr,
        (__nv_bfloat16*)(base + OFF_Q), nullptr, KMV, KE, KVD);
    pgemm_kernel<<<dim3(KE / 128, KMV / 128), 256, PG_SMEM>>>(
        (__nv_bfloat16*)(base + OFF_VN), (__nv_bfloat16*)(base + OFF_WVV),
        bvv, 1.0f, nullptr, nullptr,
        (__nv_bfloat16*)(base + OFF_VV), nullptr, KMV, KE, KVD);
    // 7: fused bidirectional attention
    attn2_kernel<<<KB * KH * ANS, 256, AT_SMEM>>>();
    // 8-10: merge + output projections
    merge_kernel<<<2048, 256>>>();
    pgemm_kernel<<<dim3(KVD / 128, KMV / 128), 256, PG_SMEM>>>(
        (__nv_bfloat16*)(base + OFF_OV), (__nv_bfloat16*)(base + OFF_WOV),
        bov, 1.0f, v, gv, nullptr, outv, KMV, KVD, KE);
    gemm_kernel<<<dim3(KLD / GBN, KML / GBM), 256>>>(
        (__nv_bfloat16*)(base + OFF_MG), (__nv_bfloat16*)(base + OFF_WOL),
        bol, 1.0f, l, gl, nullptr, outl, KML, KLD, KE);
}